// round 1
// baseline (speedup 1.0000x reference)
#include <cuda_runtime.h>

#define HEPS 1e-8f
#define HMAX_NORM 20.0f

// Sum across the 8-lane subgroup (groups are 8-lane aligned within the warp,
// so xor-shuffles with masks 1,2,4 stay inside the group).
__device__ __forceinline__ float grp_reduce8(float v) {
    v += __shfl_xor_sync(0xffffffffu, v, 1);
    v += __shfl_xor_sync(0xffffffffu, v, 2);
    v += __shfl_xor_sync(0xffffffffu, v, 4);
    return v;
}

__global__ void __launch_bounds__(256)
hyperbolic_expmap_kernel(const float4* __restrict__ x,
                         const float4* __restrict__ v,
                         float4* __restrict__ out,
                         int nrows)
{
    int tid = blockIdx.x * blockDim.x + threadIdx.x;
    int row = tid >> 3;        // 8 threads per row (D=32 -> 8 x float4)
    int sub = tid & 7;
    if (row >= nrows) return;
    const bool lead = (sub == 0);   // this lane holds element 0 (time coord)

    long idx = (long)row * 8 + sub;
    float4 x4 = x[idx];
    float4 v4 = v[idx];
    float xr[4] = {x4.x, x4.y, x4.z, x4.w};
    float vr[4] = {v4.x, v4.y, v4.z, v4.w};

    // ---- 1. project x to hyperboloid ----
    // s = sum of squares of space components (indices 1..31)
    float s = 0.f;
#pragma unroll
    for (int i = 0; i < 4; i++) {
        float sq = xr[i] * xr[i];
        if (lead && i == 0) sq = 0.f;   // exclude time coord
        s += sq;
    }
    s = grp_reduce8(s);
    float time_new, scale;
    if (s < HEPS) { time_new = sqrtf(1.f + HEPS); scale = 0.f; }
    else          { time_new = sqrtf(1.f + s);    scale = 1.f; }
#pragma unroll
    for (int i = 0; i < 4; i++) xr[i] *= scale;
    if (lead) xr[0] = time_new;

    // ---- 2. project v to tangent at x ----
    // Minkowski inner: -x0*v0 + sum_{1..31} x_i*v_i
    float inner = 0.f;
#pragma unroll
    for (int i = 0; i < 4; i++) {
        float p = xr[i] * vr[i];
        if (lead && i == 0) p = -p;
        inner += p;
    }
    inner = grp_reduce8(inner);
#pragma unroll
    for (int i = 0; i < 4; i++) vr[i] = fmaf(inner, xr[i], vr[i]);

    float check = 0.f;
#pragma unroll
    for (int i = 0; i < 4; i++) {
        float p = xr[i] * vr[i];
        if (lead && i == 0) p = -p;
        check += p;
    }
    check = grp_reduce8(check);
    if (fabsf(check) > HEPS) {       // uniform within the 8-lane group
#pragma unroll
        for (int i = 0; i < 4; i++) vr[i] = fmaf(-check, xr[i], vr[i]);
    }

    // ---- 3. minkowski norm of v ----
    float vv = 0.f;
#pragma unroll
    for (int i = 0; i < 4; i++) {
        float p = vr[i] * vr[i];
        if (lead && i == 0) p = -p;
        vv += p;
    }
    vv = grp_reduce8(vv);
    float a = fabsf(vv);
    float vn = (a < HEPS) ? (sqrtf(a) * 0.5f) : sqrtf(a);
    vn = fminf(vn, HMAX_NORM);

    float c1, c2;
    if (vn < HEPS) { c1 = 1.f; c2 = 0.f; }
    else           { c1 = coshf(vn); c2 = sinhf(vn) / fmaxf(vn, HEPS); }

    // ---- 4. result = c1*x + c2*v ----
    float r[4];
#pragma unroll
    for (int i = 0; i < 4; i++) r[i] = c1 * xr[i] + c2 * vr[i];

    // ---- 5. project result to hyperboloid ----
    float s2 = 0.f;
#pragma unroll
    for (int i = 0; i < 4; i++) {
        float sq = r[i] * r[i];
        if (lead && i == 0) sq = 0.f;
        s2 += sq;
    }
    s2 = grp_reduce8(s2);
    float t2, sc2;
    if (s2 < HEPS) { t2 = sqrtf(1.f + HEPS); sc2 = 0.f; }
    else           { t2 = sqrtf(1.f + s2);   sc2 = 1.f; }
#pragma unroll
    for (int i = 0; i < 4; i++) r[i] *= sc2;
    if (lead) r[0] = t2;

    out[idx] = make_float4(r[0], r[1], r[2], r[3]);
}

extern "C" void kernel_launch(void* const* d_in, const int* in_sizes, int n_in,
                              void* d_out, int out_size) {
    const float4* x = (const float4*)d_in[0];
    const float4* v = (const float4*)d_in[1];
    float4* out = (float4*)d_out;
    int nrows = in_sizes[0] / 32;
    const int threads = 256;
    long total = (long)nrows * 8;
    int blocks = (int)((total + threads - 1) / threads);
    hyperbolic_expmap_kernel<<<blocks, threads>>>(x, v, out, nrows);
}

// round 2
// speedup vs baseline: 1.0811x; 1.0811x over previous
#include <cuda_runtime.h>

#define HEPS 1e-8f
#define HMAX_NORM 20.0f

__device__ __forceinline__ float grp_reduce8(float v) {
    v += __shfl_xor_sync(0xffffffffu, v, 1);
    v += __shfl_xor_sync(0xffffffffu, v, 2);
    v += __shfl_xor_sync(0xffffffffu, v, 4);
    return v;
}

__global__ void __launch_bounds__(256)
hyperbolic_expmap_kernel(const float4* __restrict__ x,
                         const float4* __restrict__ v,
                         float4* __restrict__ out,
                         int nrows)
{
    int tid = blockIdx.x * blockDim.x + threadIdx.x;
    int row = tid >> 3;        // 8 threads per row (D=32 -> 8 x float4)
    int sub = tid & 7;
    if (row >= nrows) return;
    const bool lead = (sub == 0);   // this lane holds element 0 (time coord)

    long idx = (long)row * 8 + sub;
    float4 x4 = x[idx];
    float4 v4 = v[idx];
    float xr[4] = {x4.x, x4.y, x4.z, x4.w};
    float vr[4] = {v4.x, v4.y, v4.z, v4.w};

    // ---- 1. project x to hyperboloid ----
    float s = 0.f;
#pragma unroll
    for (int i = 0; i < 4; i++) {
        float sq = xr[i] * xr[i];
        if (lead && i == 0) sq = 0.f;   // exclude time coord
        s += sq;
    }
    s = grp_reduce8(s);
    float time_new, scale;
    if (s < HEPS) { time_new = sqrtf(1.f + HEPS); scale = 0.f; }
    else          { time_new = sqrtf(1.f + s);    scale = 1.f; }
#pragma unroll
    for (int i = 0; i < 4; i++) xr[i] *= scale;
    if (lead) xr[0] = time_new;

    // ---- 2. inner = <x,v>_M and vv0 = <v,v>_M in one pass ----
    float pi = 0.f, pv = 0.f;
#pragma unroll
    for (int i = 0; i < 4; i++) {
        float xv = xr[i] * vr[i];
        float vq = vr[i] * vr[i];
        if (lead && i == 0) { xv = -xv; vq = -vq; }
        pi += xv;
        pv += vq;
    }
#pragma unroll
    for (int m = 1; m <= 4; m <<= 1) {
        pi += __shfl_xor_sync(0xffffffffu, pi, m);
        pv += __shfl_xor_sync(0xffffffffu, pv, m);
    }
    float inner = pi;

    // v_proj = v + inner*x   (tangent "check" correction is fp-noise: skipped)
#pragma unroll
    for (int i = 0; i < 4; i++) vr[i] = fmaf(inner, xr[i], vr[i]);

    // <v_p, v_p>_M = <v,v>_M + inner^2   (since <x,x>_M = -1, <x,v_p>_M = 0)
    float vv = fmaf(inner, inner, pv);

    // ---- 3. minkowski norm ----
    float a = fabsf(vv);
    float vn = (a < HEPS) ? (sqrtf(a) * 0.5f) : sqrtf(a);
    vn = fminf(vn, HMAX_NORM);

    float c1, c2;
    if (vn < HEPS) { c1 = 1.f; c2 = 0.f; }
    else {
        float e  = __expf(vn);
        float ei = __expf(-vn);
        c1 = 0.5f * (e + ei);
        c2 = (0.5f * (e - ei)) / fmaxf(vn, HEPS);
    }

    // ---- 4. result = c1*x + c2*v_p ----
    float r[4];
#pragma unroll
    for (int i = 0; i < 4; i++) r[i] = fmaf(c2, vr[i], c1 * xr[i]);

    // ---- 5. project result: s2 = c2^2*vv - c1^2 + r0^2 (analytic) ----
    float vp0 = __shfl_sync(0xffffffffu, vr[0], 0, 8);   // lead's v_proj[0]
    float r0  = fmaf(c2, vp0, c1 * time_new);
    float s2  = fmaf(c2 * c2, vv, fmaf(r0, r0, -c1 * c1));

    float t2, sc2;
    if (s2 < HEPS) { t2 = sqrtf(1.f + HEPS); sc2 = 0.f; }
    else           { t2 = sqrtf(1.f + s2);   sc2 = 1.f; }
#pragma unroll
    for (int i = 0; i < 4; i++) r[i] *= sc2;
    if (lead) r[0] = t2;

    out[idx] = make_float4(r[0], r[1], r[2], r[3]);
}

extern "C" void kernel_launch(void* const* d_in, const int* in_sizes, int n_in,
                              void* d_out, int out_size) {
    const float4* x = (const float4*)d_in[0];
    const float4* v = (const float4*)d_in[1];
    float4* out = (float4*)d_out;
    int nrows = in_sizes[0] / 32;
    const int threads = 256;
    long total = (long)nrows * 8;
    int blocks = (int)((total + threads - 1) / threads);
    hyperbolic_expmap_kernel<<<blocks, threads>>>(x, v, out, nrows);
}

// round 3
// speedup vs baseline: 1.1250x; 1.0406x over previous
#include <cuda_runtime.h>

#define HEPS 1e-8f
#define HMAX_NORM 20.0f

__global__ void __launch_bounds__(256)
hyperbolic_expmap_kernel(const float4* __restrict__ x,
                         const float4* __restrict__ v,
                         float4* __restrict__ out,
                         int nrows)
{
    int tid = blockIdx.x * blockDim.x + threadIdx.x;
    int row = tid >> 2;        // 4 threads per row, each owns 2 x float4
    int sub = tid & 3;
    if (row >= nrows) return;
    const bool lead = (sub == 0);   // owns the time coordinate (element 0)

    long idx0 = (long)row * 8 + sub;   // chunk sub
    long idx1 = idx0 + 4;              // chunk sub+4

    // Issue all 4 loads up front (MLP=4)
    float4 xa = x[idx0];
    float4 xb = x[idx1];
    float4 va = v[idx0];
    float4 vb = v[idx1];

    float xr[8] = {xa.x, xa.y, xa.z, xa.w, xb.x, xb.y, xb.z, xb.w};
    float vr[8] = {va.x, va.y, va.z, va.w, vb.x, vb.y, vb.z, vb.w};

    // ---- single fused reduction pass over ORIGINAL data ----
    // s   = sum of squares of space components of x (exclude elem 0)
    // xv  = sum over space of x_i * v_i              (exclude elem 0)
    // vvm = Minkowski <v,v> = -v0^2 + sum_space v_i^2
    float s = 0.f, xv = 0.f, vvm = 0.f;
#pragma unroll
    for (int i = 0; i < 8; i++) {
        float xi = xr[i], vi = vr[i];
        float sq = xi * xi;
        float p  = xi * vi;
        float q  = vi * vi;
        if (lead && i == 0) { sq = 0.f; p = 0.f; q = -q; }
        s += sq; xv += p; vvm += q;
    }
#pragma unroll
    for (int m = 1; m <= 2; m <<= 1) {
        s   += __shfl_xor_sync(0xffffffffu, s,   m);
        xv  += __shfl_xor_sync(0xffffffffu, xv,  m);
        vvm += __shfl_xor_sync(0xffffffffu, vvm, m);
    }
    float v0 = __shfl_sync(0xffffffffu, vr[0], 0, 4);  // time comp of v

    // ---- projection of x + Minkowski inner, analytically ----
    bool tiny = (s < HEPS);
    float t     = sqrtf(1.f + (tiny ? HEPS : s));   // new time coord of x
    float scale = tiny ? 0.f : 1.f;
    float inner = fmaf(-t, v0, scale * xv);         // <x_proj, v>_M

    // v_proj = v + inner * x_proj ; <v_p,v_p>_M = <v,v>_M + inner^2
#pragma unroll
    for (int i = 0; i < 8; i++) {
        float xp = scale * xr[i];
        if (lead && i == 0) xp = t;
        xr[i] = xp;
        vr[i] = fmaf(inner, xp, vr[i]);
    }
    float vv = fmaf(inner, inner, vvm);

    // ---- minkowski norm + cosh/sinh coefficients ----
    float a  = fabsf(vv);
    float vn = (a < HEPS) ? (sqrtf(a) * 0.5f) : sqrtf(a);
    vn = fminf(vn, HMAX_NORM);
    float c1, c2;
    if (vn < HEPS) { c1 = 1.f; c2 = 0.f; }
    else {
        float e  = __expf(vn);
        float ei = __expf(-vn);
        c1 = 0.5f * (e + ei);
        c2 = (0.5f * (e - ei)) / fmaxf(vn, HEPS);
    }

    // ---- result = c1*x_proj + c2*v_proj (reuse xr) ----
#pragma unroll
    for (int i = 0; i < 8; i++) xr[i] = fmaf(c2, vr[i], c1 * xr[i]);

    // ---- final projection, analytic:  s2 = c2^2*vv + r0^2 - c1^2 ----
    float vp0 = fmaf(inner, t, v0);           // lead's v_proj[0], no shuffle
    float r0  = fmaf(c2, vp0, c1 * t);
    float s2  = fmaf(c2 * c2, vv, fmaf(r0, r0, -c1 * c1));

    bool tiny2 = (s2 < HEPS);
    float t2  = sqrtf(1.f + (tiny2 ? HEPS : s2));
    float sc2 = tiny2 ? 0.f : 1.f;
#pragma unroll
    for (int i = 0; i < 8; i++) xr[i] *= sc2;
    if (lead) xr[0] = t2;

    out[idx0] = make_float4(xr[0], xr[1], xr[2], xr[3]);
    out[idx1] = make_float4(xr[4], xr[5], xr[6], xr[7]);
}

extern "C" void kernel_launch(void* const* d_in, const int* in_sizes, int n_in,
                              void* d_out, int out_size) {
    const float4* x = (const float4*)d_in[0];
    const float4* v = (const float4*)d_in[1];
    float4* out = (float4*)d_out;
    int nrows = in_sizes[0] / 32;
    const int threads = 256;
    long total = (long)nrows * 4;
    int blocks = (int)((total + threads - 1) / threads);
    hyperbolic_expmap_kernel<<<blocks, threads>>>(x, v, out, nrows);
}